// round 12
// baseline (speedup 1.0000x reference)
#include <cuda_runtime.h>
#include <cuda_bf16.h>
#include <math.h>

#define BB   64
#define SS   512
#define EE   128
#define HH   128
#define GG   512          // 4*H
#define FWW  6
#define WW   507          // S - FW + 1
#define MT   64           // windows per CTA (2 halves of 32)
#define NTHREADS 256
#define NTILES 8          // 8*64 >= 507
#define NCTAS (NTILES*BB) // 512 CTAs

#define W_BYTES (GG*EE*2)        // 131072: resident bf16 weight (w_ih, then w_hh)
#define EH_ROWS 80               // emb tile rows (69 real, clamped to 79) / h tile (64 rows)
#define EH_BYTES (EH_ROWS*256)   // 20480
#define X_ROWS  69               // tokens w0..w0+68
#define X_BYTES (X_ROWS*1024)    // 70656 (stride 1024, +48B/row rotation)
#define SMEM_F  (W_BYTES + EH_BYTES + X_BYTES)   // 222208 < 227KB

// Scratch (device globals: allocation is forbidden)
__device__ __align__(16) __nv_bfloat16 g_wih16[GG * EE];
__device__ __align__(16) __nv_bfloat16 g_whh16[GG * HH];
__device__ unsigned g_featu[BB * HH];   // order-encoded float, atomicMax pooling
__device__ unsigned g_done;             // CTA completion counter

// ---------------------------------------------------------------------------
__device__ __forceinline__ unsigned sptr(const void* p) {
    return (unsigned)__cvta_generic_to_shared(p);
}
__device__ __forceinline__ float tanha_(float x) {
    float y; asm("tanh.approx.f32 %0, %1;" : "=f"(y) : "f"(x)); return y;
}
__device__ __forceinline__ float sigm_(float x) {
    return fmaf(0.5f, tanha_(0.5f * x), 0.5f);
}
__device__ __forceinline__ unsigned encf_(float x) {
    unsigned u = __float_as_uint(x);
    return (u & 0x80000000u) ? ~u : (u | 0x80000000u);
}
__device__ __forceinline__ float decf_(unsigned k) {
    return __uint_as_float((k & 0x80000000u) ? (k & 0x7fffffffu) : ~k);
}
__device__ __forceinline__ void ldsm4(unsigned* r, unsigned addr) {
    asm volatile("ldmatrix.sync.aligned.m8n8.x4.shared.b16 {%0,%1,%2,%3}, [%4];"
                 : "=r"(r[0]), "=r"(r[1]), "=r"(r[2]), "=r"(r[3]) : "r"(addr));
}
__device__ __forceinline__ void mma_bf16(float* d, const unsigned* a, unsigned b0, unsigned b1) {
    asm("mma.sync.aligned.m16n8k16.row.col.f32.bf16.bf16.f32 "
        "{%0,%1,%2,%3},{%4,%5,%6,%7},{%8,%9},{%0,%1,%2,%3};"
        : "+f"(d[0]), "+f"(d[1]), "+f"(d[2]), "+f"(d[3])
        : "r"(a[0]), "r"(a[1]), "r"(a[2]), "r"(a[3]), "r"(b0), "r"(b1));
}
__device__ __forceinline__ unsigned packbf2(float lo, float hi) {
    __nv_bfloat162 p = __float22bfloat162_rn(make_float2(lo, hi));
    return *reinterpret_cast<unsigned*>(&p);
}
__device__ __forceinline__ float2 unpackbf2(unsigned u) {
    return __bfloat1622float2(*reinterpret_cast<__nv_bfloat162*>(&u));
}
// X buffer: stride 1024, rotate 48B per row (conflict-free)
__device__ __forceinline__ unsigned xoff(int row, int colbyte) {
    return (unsigned)(row * 1024 + ((colbyte + row * 48) & 1023));
}

// ---------------------------------------------------------------------------
// Kernel 0: weights fp32 -> bf16; reset pool accumulators + counter
// ---------------------------------------------------------------------------
__global__ void prep_kernel(const float* __restrict__ w_ih, const float* __restrict__ w_hh) {
    int i = blockIdx.x * blockDim.x + threadIdx.x;
    if (i < GG * EE) {
        g_wih16[i] = __float2bfloat16(w_ih[i]);
        g_whh16[i] = __float2bfloat16(w_hh[i]);
    }
    if (i < BB * HH) g_featu[i] = 0u;
    if (i == 0) g_done = 0u;
}

// ---------------------------------------------------------------------------
// Stage a full 512x128 bf16 weight matrix into smem, 16B-chunk swizzled
// ---------------------------------------------------------------------------
__device__ __forceinline__ void stage_w(const __nv_bfloat16* __restrict__ src, char* w_sc, int tid) {
    const uint4* s = (const uint4*)src;
    uint4* d = (uint4*)w_sc;
    #pragma unroll
    for (int i = 0; i < 32; ++i) {
        int id  = i * 256 + tid;
        int gs  = id >> 11;
        int rem = id & 2047;
        int n   = rem >> 4;
        int c   = rem & 15;
        d[gs * 2048 + n * 16 + (c ^ (n & 7))] = s[id];
    }
}

// ---------------------------------------------------------------------------
// GEMM: acc += A(MTILES*16 x 128, smem @aBase) @ W^T (all 4 gate chunks)
// Warp tile: M = MTILES*16 shared by all warps, N = 16 per chunk (nw0 slice).
// ---------------------------------------------------------------------------
template<int MTILES>
__device__ __forceinline__ void gemmT(unsigned aBase, unsigned bB,
                                      int rs, int qb, int qh,
                                      float (&acc)[4][2][2][4]) {
    #pragma unroll
    for (int ks = 0; ks < 8; ++ks) {
        unsigned af[MTILES][4];
        unsigned ca = ((unsigned)((2 * ks + qh) ^ rs)) << 4;
        #pragma unroll
        for (int mt = 0; mt < MTILES; ++mt) ldsm4(af[mt], aBase + mt * 4096 + ca);
        unsigned cb = ((unsigned)((2 * ks + qb) ^ rs)) << 4;
        #pragma unroll
        for (int gs = 0; gs < 4; ++gs) {
            unsigned bf[4];
            ldsm4(bf, bB + gs * 32768 + cb);
            #pragma unroll
            for (int mt = 0; mt < MTILES; ++mt) {
                mma_bf16(acc[gs][mt][0], af[mt], bf[0], bf[1]);
                mma_bf16(acc[gs][mt][1], af[mt], bf[2], bf[3]);
            }
        }
    }
}

// ---------------------------------------------------------------------------
// Load X rows [row0..row0+32) into acc; cell update; half-index helpers
// ---------------------------------------------------------------------------
__device__ __forceinline__ void load_x(const char* x_sc, int row0, int g, int tq, int nw0,
                                       float (&acc)[4][2][2][4]) {
    #pragma unroll
    for (int mt = 0; mt < 2; ++mt)
        #pragma unroll
        for (int hh = 0; hh < 2; ++hh) {
            int r = row0 + mt * 16 + g + 8 * hh;
            #pragma unroll
            for (int gs = 0; gs < 4; ++gs)
                #pragma unroll
                for (int nt = 0; nt < 2; ++nt) {
                    int colb = (gs * 128 + nw0 + nt * 8 + 2 * tq) * 2;
                    float2 v = unpackbf2(*(const unsigned*)(x_sc + xoff(r, colb)));
                    acc[gs][mt][nt][2 * hh]     = v.x;
                    acc[gs][mt][nt][2 * hh + 1] = v.y;
                }
        }
}

__device__ __forceinline__ void cell(const float (&acc)[4][2][2][4],
                                     float (&c)[2][2][4], float (&h)[2][2][4]) {
    #pragma unroll
    for (int mt = 0; mt < 2; ++mt)
        #pragma unroll
        for (int nt = 0; nt < 2; ++nt)
            #pragma unroll
            for (int q = 0; q < 4; ++q) {
                float gi = acc[0][mt][nt][q], gf = acc[1][mt][nt][q];
                float gg = acc[2][mt][nt][q], go = acc[3][mt][nt][q];
                float cn = sigm_(gf) * c[mt][nt][q] + sigm_(gi) * tanha_(gg);
                c[mt][nt][q] = cn;
                h[mt][nt][q] = sigm_(go) * tanha_(cn);
            }
}

__device__ __forceinline__ void store_h(char* eh, int half, const float (&h)[2][2][4],
                                        int g, int tq, int nw0) {
    #pragma unroll
    for (int mt = 0; mt < 2; ++mt)
        #pragma unroll
        for (int nt = 0; nt < 2; ++nt)
            #pragma unroll
            for (int hh = 0; hh < 2; ++hh) {
                int r   = half * 32 + mt * 16 + g + 8 * hh;
                int cb0 = (nw0 >> 3) + nt;
                *(unsigned*)(eh + r * 256 + ((cb0 ^ g) << 4) + 4 * tq) =
                    packbf2(h[mt][nt][2 * hh], h[mt][nt][2 * hh + 1]);
            }
}

// ---------------------------------------------------------------------------
// Fused kernel: X in smem, 6-step LSTM (two sequential 32-row halves through
// ONE shared acc -> no register spills), pool + FC
// ---------------------------------------------------------------------------
__global__ __launch_bounds__(NTHREADS, 1)
void lstm_kernel(const int* __restrict__ inputs,
                 const float* __restrict__ embed,
                 const float* __restrict__ b_ih,
                 const float* __restrict__ b_hh,
                 const float* __restrict__ fc_w,
                 const float* __restrict__ fc_b,
                 float* __restrict__ out)
{
    extern __shared__ char smem[];
    char* w_sc = smem;                        // weights (w_ih, then w_hh)
    char* eh   = smem + W_BYTES;              // emb tile (80 rows) -> h tile (64 rows)
    char* x_sc = smem + W_BYTES + EH_BYTES;   // X: 69 rows, rotated stride-1024

    const int tid  = threadIdx.x;
    const int lane = tid & 31;
    const int wid  = tid >> 5;
    const int g    = lane >> 2;
    const int tq   = lane & 3;
    const int rs   = lane & 7;
    const int qb   = (lane >> 3) & 1;
    const int qh   = (lane >> 4) & 1;
    const int nw0  = wid * 16;                // warp's 16-col slice per gate chunk

    const int b    = blockIdx.y;
    const int w0   = blockIdx.x * MT;
    const int wlim = WW - w0;                 // valid local windows

    // ---- stage w_ih + gather embeddings (rows 0..79, clamped tokens) ----
    stage_w(g_wih16, w_sc, tid);
    {
        // 80 rows x 16 chunks = 1280 units, 5 per thread
        #pragma unroll
        for (int i = 0; i < 5; ++i) {
            int id = i * 256 + tid;
            int r  = id >> 4, c = id & 15;
            int tok = min(w0 + r, SS - 1);
            const float4* erow = (const float4*)(embed + (size_t)inputs[b * SS + tok] * EE);
            float4 v0 = erow[2 * c], v1 = erow[2 * c + 1];
            uint4 u;
            u.x = packbf2(v0.x, v0.y); u.y = packbf2(v0.z, v0.w);
            u.z = packbf2(v1.x, v1.y); u.w = packbf2(v1.z, v1.w);
            *(uint4*)(eh + r * 256 + ((c ^ (r & 7)) << 4)) = u;
        }
    }

    unsigned ehS = sptr(eh), wS = sptr(w_sc);
    unsigned aBase = ehS + (rs + 8 * qb) * 256;
    unsigned bB    = wS + (nw0 + rs + 8 * qh) * 256;

    __syncthreads();   // emb + w_ih staged

    float acc[4][2][2][4];   // ONE shared accumulator for every pass

    // ---- X = emb @ w_ih^T + bias : 3 passes (rows 0-31, 32-63, 64-79) ----
    {
        float bias[4][2][2];
        #pragma unroll
        for (int gs = 0; gs < 4; ++gs)
            #pragma unroll
            for (int nt = 0; nt < 2; ++nt) {
                int col = gs * 128 + nw0 + nt * 8 + 2 * tq;
                float2 bi = *(const float2*)&b_ih[col];
                float2 bh = *(const float2*)&b_hh[col];
                bias[gs][nt][0] = bi.x + bh.x;
                bias[gs][nt][1] = bi.y + bh.y;
            }

        #pragma unroll
        for (int pass = 0; pass < 3; ++pass) {
            const int row0 = pass * 32;
            #pragma unroll
            for (int gs = 0; gs < 4; ++gs)
                #pragma unroll
                for (int mt = 0; mt < 2; ++mt)
                    #pragma unroll
                    for (int nt = 0; nt < 2; ++nt) {
                        acc[gs][mt][nt][0] = bias[gs][nt][0]; acc[gs][mt][nt][1] = bias[gs][nt][1];
                        acc[gs][mt][nt][2] = bias[gs][nt][0]; acc[gs][mt][nt][3] = bias[gs][nt][1];
                    }
            if (pass < 2) gemmT<2>(aBase + row0 * 256, bB, rs, qb, qh, acc);
            else          gemmT<1>(aBase + row0 * 256, bB, rs, qb, qh, acc);

            const int mmax = (pass < 2) ? 2 : 1;
            for (int mt = 0; mt < mmax; ++mt)
                #pragma unroll
                for (int hh = 0; hh < 2; ++hh) {
                    int r = row0 + mt * 16 + g + 8 * hh;
                    if (r < X_ROWS) {
                        #pragma unroll
                        for (int gs = 0; gs < 4; ++gs)
                            #pragma unroll
                            for (int nt = 0; nt < 2; ++nt) {
                                int colb = (gs * 128 + nw0 + nt * 8 + 2 * tq) * 2;
                                *(unsigned*)(x_sc + xoff(r, colb)) =
                                    packbf2(acc[gs][mt][nt][2 * hh], acc[gs][mt][nt][2 * hh + 1]);
                            }
                    }
                }
        }
    }

    __syncthreads();              // X done; emb + w_ih reads done
    stage_w(g_whh16, w_sc, tid);  // W := w_hh (eh becomes h tile, 64 rows)
    __syncthreads();

    // ---- recurrence: halves A (rows 0-31) and B (rows 32-63), sequential ----
    float cA[2][2][4] = {}, cB[2][2][4] = {};
    float hA[2][2][4], hB[2][2][4];
    float pmax[2][2] = {{-3.4e38f, -3.4e38f}, {-3.4e38f, -3.4e38f}};

    for (int t = 0; t < FWW; ++t) {
        // half A
        load_x(x_sc, 0 + t, g, tq, nw0, acc);
        if (t > 0) gemmT<2>(aBase, bB, rs, qb, qh, acc);          // reads h_A(t-1)
        cell(acc, cA, hA);
        // half B (same acc array — register reuse forced)
        load_x(x_sc, 32 + t, g, tq, nw0, acc);
        if (t > 0) gemmT<2>(aBase + 8192, bB, rs, qb, qh, acc);   // reads h_B(t-1)
        cell(acc, cB, hB);

        if (t < FWW - 1) {
            __syncthreads();   // all ldsm reads of h(t-1) complete
            store_h(eh, 0, hA, g, tq, nw0);
            store_h(eh, 1, hB, g, tq, nw0);
            __syncthreads();   // h(t) visible
        } else {
            #pragma unroll
            for (int mt = 0; mt < 2; ++mt)
                #pragma unroll
                for (int nt = 0; nt < 2; ++nt)
                    #pragma unroll
                    for (int hh = 0; hh < 2; ++hh) {
                        int rA = mt * 16 + g + 8 * hh;
                        if (rA < wlim) {
                            pmax[nt][0] = fmaxf(pmax[nt][0], hA[mt][nt][2 * hh]);
                            pmax[nt][1] = fmaxf(pmax[nt][1], hA[mt][nt][2 * hh + 1]);
                        }
                        if (rA + 32 < wlim) {
                            pmax[nt][0] = fmaxf(pmax[nt][0], hB[mt][nt][2 * hh]);
                            pmax[nt][1] = fmaxf(pmax[nt][1], hB[mt][nt][2 * hh + 1]);
                        }
                    }
        }
    }

    // ---- pool: shfl-reduce over g, one atomicMax per column ----
    #pragma unroll
    for (int nt = 0; nt < 2; ++nt)
        #pragma unroll
        for (int e = 0; e < 2; ++e) {
            float m = pmax[nt][e];
            m = fmaxf(m, __shfl_xor_sync(0xffffffffu, m, 4));
            m = fmaxf(m, __shfl_xor_sync(0xffffffffu, m, 8));
            m = fmaxf(m, __shfl_xor_sync(0xffffffffu, m, 16));
            pmax[nt][e] = m;
        }
    if (g == 0) {
        #pragma unroll
        for (int nt = 0; nt < 2; ++nt)
            #pragma unroll
            for (int e = 0; e < 2; ++e)
                atomicMax(&g_featu[b * HH + nw0 + nt * 8 + 2 * tq + e], encf_(pmax[nt][e]));
    }

    // ---- last CTA computes the FC ----
    __threadfence();
    __shared__ unsigned s_last;
    if (tid == 0) {
        unsigned old = atomicAdd(&g_done, 1u);
        s_last = (old == (unsigned)(NCTAS - 1)) ? 1u : 0u;
    }
    __syncthreads();
    if (s_last) {
        int pair = tid >> 1;          // 0..127
        int fb   = pair >> 1;         // batch
        int o    = pair & 1;          // output class
        int kh   = tid & 1;           // k half
        float s = 0.0f;
        #pragma unroll 8
        for (int k = kh * 64; k < kh * 64 + 64; ++k) {
            unsigned enc = atomicAdd(&g_featu[fb * HH + k], 0u);   // coherent read
            s += decf_(enc) * fc_w[o * HH + k];
        }
        s += __shfl_xor_sync(0xffffffffu, s, 1);
        if (kh == 0) out[fb * 2 + o] = s + fc_b[o];
    }
}

// ---------------------------------------------------------------------------
extern "C" void kernel_launch(void* const* d_in, const int* in_sizes, int n_in,
                              void* d_out, int out_size)
{
    const int*   inputs = (const int*)  d_in[0];
    // d_in[1] = lengths : unused by the reference
    const float* embed  = (const float*)d_in[2];
    const float* w_ih   = (const float*)d_in[3];
    const float* w_hh   = (const float*)d_in[4];
    const float* b_ih   = (const float*)d_in[5];
    const float* b_hh   = (const float*)d_in[6];
    const float* fc_w   = (const float*)d_in[7];
    const float* fc_b   = (const float*)d_in[8];
    float* out = (float*)d_out;

    cudaFuncSetAttribute(lstm_kernel, cudaFuncAttributeMaxDynamicSharedMemorySize, SMEM_F);

    prep_kernel<<<(GG * EE + 255) / 256, 256>>>(w_ih, w_hh);
    lstm_kernel<<<dim3(NTILES, BB), NTHREADS, SMEM_F>>>(inputs, embed, b_ih, b_hh,
                                                        fc_w, fc_b, out);
}

// round 13
// speedup vs baseline: 1.1035x; 1.1035x over previous
#include <cuda_runtime.h>
#include <cuda_bf16.h>
#include <cuda_fp16.h>
#include <math.h>

#define BB   64
#define SS   512
#define EE   128
#define HH   128
#define GG   512          // 4*H
#define FWW  6
#define WW   507          // S - FW + 1
#define MT   64           // windows per CTA (2 halves of 32)
#define NTHREADS 256
#define NTILES 8          // 8*64 >= 507
#define NCTAS (NTILES*BB) // 512 CTAs

#define W_BYTES (GG*EE*2)        // 131072: resident bf16 weight (w_ih, then w_hh)
#define A_ROWS  80               // emb tile rows (69 real, clamped) / h tile (64 rows)
#define A_BYTES (A_ROWS*256)     // 20480
#define X_ROWS  69               // tokens w0..w0+68
#define X_STRIDE 1040            // 512 bf16 + 16B pad
#define X_BYTES (X_ROWS*X_STRIDE)        // 71760
#define SMEM_F  (W_BYTES + A_BYTES + X_BYTES)   // 223312 <= 227KB

// Scratch (device globals: allocation is forbidden)
__device__ __align__(16) __nv_bfloat16 g_wih16[GG * EE];
__device__ __align__(16) __nv_bfloat16 g_whh16[GG * HH];
__device__ unsigned g_featu[BB * HH];   // order-encoded float, atomicMax pooling
__device__ unsigned g_done;             // CTA completion counter

// ---------------------------------------------------------------------------
__device__ __forceinline__ unsigned sptr(const void* p) {
    return (unsigned)__cvta_generic_to_shared(p);
}
__device__ __forceinline__ float tanha_(float x) {
    float y; asm("tanh.approx.f32 %0, %1;" : "=f"(y) : "f"(x)); return y;
}
// packed sigmoid pair: sigma(x) = 0.5*tanh(0.5x)+0.5 via tanh.approx.f16x2
__device__ __forceinline__ float2 sigm2_(float x0, float x1) {
    unsigned p, t, s;
    asm("cvt.rn.f16x2.f32 %0, %1, %2;" : "=r"(p) : "f"(0.5f * x1), "f"(0.5f * x0));
    asm("tanh.approx.f16x2 %0, %1;" : "=r"(t) : "r"(p));
    asm("fma.rn.f16x2 %0, %1, %2, %2;" : "=r"(s) : "r"(t), "r"(0x38003800u)); // *0.5+0.5
    __half2 h2 = *reinterpret_cast<__half2*>(&s);
    return __half22float2(h2);
}
__device__ __forceinline__ unsigned encf_(float x) {
    unsigned u = __float_as_uint(x);
    return (u & 0x80000000u) ? ~u : (u | 0x80000000u);
}
__device__ __forceinline__ float decf_(unsigned k) {
    return __uint_as_float((k & 0x80000000u) ? (k & 0x7fffffffu) : ~k);
}
__device__ __forceinline__ void ldsm4(unsigned* r, unsigned addr) {
    asm volatile("ldmatrix.sync.aligned.m8n8.x4.shared.b16 {%0,%1,%2,%3}, [%4];"
                 : "=r"(r[0]), "=r"(r[1]), "=r"(r[2]), "=r"(r[3]) : "r"(addr));
}
__device__ __forceinline__ void mma_bf16(float* d, const unsigned* a, unsigned b0, unsigned b1) {
    asm("mma.sync.aligned.m16n8k16.row.col.f32.bf16.bf16.f32 "
        "{%0,%1,%2,%3},{%4,%5,%6,%7},{%8,%9},{%0,%1,%2,%3};"
        : "+f"(d[0]), "+f"(d[1]), "+f"(d[2]), "+f"(d[3])
        : "r"(a[0]), "r"(a[1]), "r"(a[2]), "r"(a[3]), "r"(b0), "r"(b1));
}
__device__ __forceinline__ unsigned packbf2(float lo, float hi) {
    __nv_bfloat162 p = __float22bfloat162_rn(make_float2(lo, hi));
    return *reinterpret_cast<unsigned*>(&p);
}
__device__ __forceinline__ float2 unpackbf2(unsigned u) {
    return __bfloat1622float2(*reinterpret_cast<__nv_bfloat162*>(&u));
}

// ---------------------------------------------------------------------------
// Kernel 0: weights fp32 -> bf16; reset pool accumulators + counter
// ---------------------------------------------------------------------------
__global__ void prep_kernel(const float* __restrict__ w_ih, const float* __restrict__ w_hh) {
    int i = blockIdx.x * blockDim.x + threadIdx.x;
    if (i < GG * EE) {
        g_wih16[i] = __float2bfloat16(w_ih[i]);
        g_whh16[i] = __float2bfloat16(w_hh[i]);
    }
    if (i < BB * HH) g_featu[i] = 0u;
    if (i == 0) g_done = 0u;
}

// ---------------------------------------------------------------------------
// Stage a full 512x128 bf16 weight matrix into smem, 16B-chunk swizzled
// ---------------------------------------------------------------------------
__device__ __forceinline__ void stage_w(const __nv_bfloat16* __restrict__ src, char* w_sc, int tid) {
    const uint4* s = (const uint4*)src;
    uint4* d = (uint4*)w_sc;
    #pragma unroll
    for (int i = 0; i < 32; ++i) {
        int id  = i * 256 + tid;
        int gs  = id >> 11;
        int rem = id & 2047;
        int n   = rem >> 4;
        int c   = rem & 15;
        d[gs * 2048 + n * 16 + (c ^ (n & 7))] = s[id];
    }
}

// ---------------------------------------------------------------------------
// Load X rows [row0..row0+32) into accumulators (smem -> regs, bf16 -> f32)
// ---------------------------------------------------------------------------
__device__ __forceinline__ void load_x(const char* x_sc, int row0, int g, int tq, int nw0,
                                       float (&acc)[4][2][2][4]) {
    #pragma unroll
    for (int mt = 0; mt < 2; ++mt)
        #pragma unroll
        for (int hh = 0; hh < 2; ++hh) {
            const char* xr = x_sc + (row0 + mt * 16 + g + 8 * hh) * X_STRIDE;
            #pragma unroll
            for (int gs = 0; gs < 4; ++gs)
                #pragma unroll
                for (int nt = 0; nt < 2; ++nt) {
                    unsigned u = *(const unsigned*)(xr + (gs * 128 + nw0 + nt * 8 + 2 * tq) * 2);
                    float2 v = unpackbf2(u);
                    acc[gs][mt][nt][2 * hh]     = v.x;
                    acc[gs][mt][nt][2 * hh + 1] = v.y;
                }
        }
}

// ---------------------------------------------------------------------------
// One phase: GEMM of one half interleaved with the cell update of the OTHER
// half (independent rows -> tensor/MUFU pipes overlap).
// CM: 0 = no cell, 1 = cell + store h to smem, 2 = cell + pool max
// ---------------------------------------------------------------------------
template<bool DO_GEMM, int CM>
__device__ __forceinline__ void run_phase(
    unsigned aB0, unsigned aB1, unsigned bB,
    float (&accG)[4][2][2][4], float (&accC)[4][2][2][4],
    float (&cC)[2][2][4], float (&pmax)[2][2],
    char* a_store, int g, int tq, int rs, int qb, int qh, int nw0,
    int wrow0, int wlim)
{
    #pragma unroll
    for (int ks = 0; ks < 8; ++ks) {
        if (DO_GEMM) {
            unsigned af0[4], af1[4];
            unsigned ca = ((unsigned)((2 * ks + qh) ^ rs)) << 4;
            ldsm4(af0, aB0 + ca);
            ldsm4(af1, aB1 + ca);
            unsigned cb = ((unsigned)((2 * ks + qb) ^ rs)) << 4;
            #pragma unroll
            for (int gs = 0; gs < 4; ++gs) {
                unsigned bf[4];
                ldsm4(bf, bB + gs * 32768 + cb);
                mma_bf16(accG[gs][0][0], af0, bf[0], bf[1]);
                mma_bf16(accG[gs][0][1], af0, bf[2], bf[3]);
                mma_bf16(accG[gs][1][0], af1, bf[0], bf[1]);
                mma_bf16(accG[gs][1][1], af1, bf[2], bf[3]);
            }
        }
        if (CM) {
            const int mt = ks >> 2, nt = (ks >> 1) & 1, hh = ks & 1;
            float gi0 = accC[0][mt][nt][2 * hh], gi1 = accC[0][mt][nt][2 * hh + 1];
            float gf0 = accC[1][mt][nt][2 * hh], gf1 = accC[1][mt][nt][2 * hh + 1];
            float gg0 = accC[2][mt][nt][2 * hh], gg1 = accC[2][mt][nt][2 * hh + 1];
            float go0 = accC[3][mt][nt][2 * hh], go1 = accC[3][mt][nt][2 * hh + 1];
            float2 si = sigm2_(gi0, gi1);
            float2 sf = sigm2_(gf0, gf1);
            float2 so = sigm2_(go0, go1);
            float cn0 = sf.x * cC[mt][nt][2 * hh]     + si.x * tanha_(gg0);
            float cn1 = sf.y * cC[mt][nt][2 * hh + 1] + si.y * tanha_(gg1);
            cC[mt][nt][2 * hh]     = cn0;
            cC[mt][nt][2 * hh + 1] = cn1;
            float h0 = so.x * tanha_(cn0);
            float h1 = so.y * tanha_(cn1);
            if (CM == 1) {
                int r   = mt * 16 + g + 8 * hh;
                int cb0 = (nw0 >> 3) + nt;
                *(unsigned*)(a_store + r * 256 + ((cb0 ^ g) << 4) + 4 * tq) = packbf2(h0, h1);
            } else {
                if (wrow0 + mt * 16 + g + 8 * hh < wlim) {   // exclude invalid windows
                    pmax[nt][0] = fmaxf(pmax[nt][0], h0);
                    pmax[nt][1] = fmaxf(pmax[nt][1], h1);
                }
            }
        }
    }
}

// ---------------------------------------------------------------------------
// Fused kernel: X = emb@w_ih^T + bias (in smem), then 6-step LSTM + pool + FC
// ---------------------------------------------------------------------------
__global__ __launch_bounds__(NTHREADS, 1)
void lstm_kernel(const int* __restrict__ inputs,
                 const float* __restrict__ embed,
                 const float* __restrict__ b_ih,
                 const float* __restrict__ b_hh,
                 const float* __restrict__ fc_w,
                 const float* __restrict__ fc_b,
                 float* __restrict__ out)
{
    extern __shared__ char smem[];
    char* w_sc = smem;                       // weights (w_ih, then w_hh)
    char* a_sc = smem + W_BYTES;             // emb tile (80 rows) / h tiles (rows 0..63)
    char* x_sc = smem + W_BYTES + A_BYTES;   // X: 69 rows x X_STRIDE

    const int tid  = threadIdx.x;
    const int lane = tid & 31;
    const int wid  = tid >> 5;
    const int g    = lane >> 2;
    const int tq   = lane & 3;
    const int rs   = lane & 7;
    const int qb   = (lane >> 3) & 1;
    const int qh   = (lane >> 4) & 1;
    const int nw0  = wid * 16;               // warp's 16-col slice per gate chunk

    const int b    = blockIdx.y;
    const int w0   = blockIdx.x * MT;
    const int wlim = WW - w0;                // valid local windows

    // ---- phase 0: stage w_ih + gather embeddings ----
    stage_w(g_wih16, w_sc, tid);
    {
        // rows 0..63: 4 threads/row, 32 cols each
        int r = tid >> 2, th = tid & 3;
        int tok = min(w0 + r, SS - 1);
        const float4* erow = (const float4*)(embed + (size_t)inputs[b * SS + tok] * EE) + th * 8;
        #pragma unroll
        for (int j = 0; j < 4; ++j) {
            float4 v0 = erow[2 * j], v1 = erow[2 * j + 1];
            uint4 u;
            u.x = packbf2(v0.x, v0.y); u.y = packbf2(v0.z, v0.w);
            u.z = packbf2(v1.x, v1.y); u.w = packbf2(v1.z, v1.w);
            int c = th * 4 + j;
            *(uint4*)(a_sc + r * 256 + ((c ^ (r & 7)) << 4)) = u;
        }
        // rows 64..79: 16 threads/row, 8 cols each
        int r2 = 64 + (tid >> 4), th2 = tid & 15;
        int tok2 = min(w0 + r2, SS - 1);
        const float4* erow2 = (const float4*)(embed + (size_t)inputs[b * SS + tok2] * EE) + th2 * 2;
        float4 w0v = erow2[0], w1v = erow2[1];
        uint4 u2;
        u2.x = packbf2(w0v.x, w0v.y); u2.y = packbf2(w0v.z, w0v.w);
        u2.z = packbf2(w1v.x, w1v.y); u2.w = packbf2(w1v.z, w1v.w);
        *(uint4*)(a_sc + r2 * 256 + ((th2 ^ (r2 & 7)) << 4)) = u2;
    }

    // bias (hoisted; added into X)
    float bias[4][2][2];
    #pragma unroll
    for (int gs = 0; gs < 4; ++gs)
        #pragma unroll
        for (int nt = 0; nt < 2; ++nt) {
            int col = gs * 128 + nw0 + nt * 8 + 2 * tq;
            float2 bi = *(const float2*)&b_ih[col];
            float2 bh = *(const float2*)&b_hh[col];
            bias[gs][nt][0] = bi.x + bh.x;
            bias[gs][nt][1] = bi.y + bh.y;
        }

    unsigned aS = sptr(a_sc), wS = sptr(w_sc);
    unsigned bB = wS + (nw0 + rs + 8 * qh) * 256;

    __syncthreads();   // emb + w_ih staged

    // ---- phase 1: X = emb @ w_ih^T + bias, three 32-row passes ----
    float accA[4][2][2][4], accB[4][2][2][4];
    float cA[2][2][4] = {}, cB[2][2][4] = {};
    float pmax[2][2] = {{-3.4e38f, -3.4e38f}, {-3.4e38f, -3.4e38f}};

    #pragma unroll
    for (int p = 0; p < 3; ++p) {
        #pragma unroll
        for (int gs = 0; gs < 4; ++gs)
            #pragma unroll
            for (int nt = 0; nt < 2; ++nt)
                #pragma unroll
                for (int mt = 0; mt < 2; ++mt) {
                    accA[gs][mt][nt][0] = bias[gs][nt][0]; accA[gs][mt][nt][1] = bias[gs][nt][1];
                    accA[gs][mt][nt][2] = bias[gs][nt][0]; accA[gs][mt][nt][3] = bias[gs][nt][1];
                }
        unsigned aP0 = aS + (32 * p + rs + 8 * qb) * 256;
        unsigned aP1 = aP0 + 4096;
        run_phase<true, 0>(aP0, aP1, bB, accA, accB, cB, pmax, a_sc,
                           g, tq, rs, qb, qh, nw0, 0, 0);
        // store X rows 32p..32p+31
        #pragma unroll
        for (int gs = 0; gs < 4; ++gs)
            #pragma unroll
            for (int mt = 0; mt < 2; ++mt)
                #pragma unroll
                for (int hh = 0; hh < 2; ++hh) {
                    int r = 32 * p + mt * 16 + g + 8 * hh;
                    if (r < X_ROWS) {
                        char* xr = x_sc + r * X_STRIDE;
                        #pragma unroll
                        for (int nt = 0; nt < 2; ++nt)
                            *(unsigned*)(xr + (gs * 128 + nw0 + nt * 8 + 2 * tq) * 2) =
                                packbf2(accA[gs][mt][nt][2 * hh], accA[gs][mt][nt][2 * hh + 1]);
                    }
                }
    }

    __syncthreads();              // all w_ih reads + emb reads done
    stage_w(g_whh16, w_sc, tid);  // W := w_hh

    unsigned aA0  = aS + (rs + 8 * qb) * 256;          // half0 h frags
    unsigned aA1  = aA0 + 4096;
    unsigned aB0_ = aS + 8192 + (rs + 8 * qb) * 256;   // half1 h frags
    unsigned aB1_ = aB0_ + 4096;

    __syncthreads();            // w_hh + X visible

    // ---- t = 0 peel: gates = X only (h = 0) ----
    load_x(x_sc, 0, g, tq, nw0, accA);
    load_x(x_sc, 32, g, tq, nw0, accB);
    run_phase<false, 1>(0, 0, 0, accB, accA, cA, pmax, a_sc,
                        g, tq, rs, qb, qh, nw0, 0, wlim);   // cell_A(0) -> store hA
    load_x(x_sc, 1, g, tq, nw0, accA);                      // hoisted X_A(1)
    __syncthreads();

    // ---- steps 1..5 ----
    for (int t = 1; t < FWW; ++t) {
        // P1: GEMM_A(t) || cell_B(t-1) + store hB ; then hoist X_B(t)
        run_phase<true, 1>(aA0, aA1, bB, accA, accB, cB, pmax, a_sc + 8192,
                           g, tq, rs, qb, qh, nw0, 32, wlim);
        load_x(x_sc, 32 + t, g, tq, nw0, accB);
        __syncthreads();

        if (t < FWW - 1) {
            // P2: GEMM_B(t) || cell_A(t) + store hA ; then hoist X_A(t+1)
            run_phase<true, 1>(aB0_, aB1_, bB, accB, accA, cA, pmax, a_sc,
                               g, tq, rs, qb, qh, nw0, 0, wlim);
            load_x(x_sc, t + 1, g, tq, nw0, accA);
            __syncthreads();
        } else {
            // final: GEMM_B(5) || cell_A(5)->pool, then cell_B(5)->pool
            run_phase<true, 2>(aB0_, aB1_, bB, accB, accA, cA, pmax, a_sc,
                               g, tq, rs, qb, qh, nw0, 0, wlim);
            run_phase<false, 2>(0, 0, 0, accA, accB, cB, pmax, a_sc,
                                g, tq, rs, qb, qh, nw0, 32, wlim);
        }
    }

    // ---- pool: reduce over rows (g) via shfl, one atomicMax per column ----
    #pragma unroll
    for (int nt = 0; nt < 2; ++nt)
        #pragma unroll
        for (int e = 0; e < 2; ++e) {
            float m = pmax[nt][e];
            m = fmaxf(m, __shfl_xor_sync(0xffffffffu, m, 4));
            m = fmaxf(m, __shfl_xor_sync(0xffffffffu, m, 8));
            m = fmaxf(m, __shfl_xor_sync(0xffffffffu, m, 16));
            pmax[nt][e] = m;
        }
    if (g == 0) {
        #pragma unroll
        for (int nt = 0; nt < 2; ++nt)
            #pragma unroll
            for (int e = 0; e < 2; ++e)
                atomicMax(&g_featu[b * HH + nw0 + nt * 8 + 2 * tq + e], encf_(pmax[nt][e]));
    }

    // ---- last CTA computes the FC ----
    __threadfence();
    __shared__ unsigned s_last;
    if (tid == 0) {
        unsigned old = atomicAdd(&g_done, 1u);
        s_last = (old == (unsigned)(NCTAS - 1)) ? 1u : 0u;
    }
    __syncthreads();
    if (s_last) {
        int pair = tid >> 1;          // 0..127
        int fb   = pair >> 1;         // batch
        int o    = pair & 1;          // output class
        int kh   = tid & 1;           // k half
        float s = 0.0f;
        #pragma unroll 8
        for (int k = kh * 64; k < kh * 64 + 64; ++k) {
            unsigned enc = atomicAdd(&g_featu[fb * HH + k], 0u);   // coherent read
            s += decf_(enc) * fc_w[o * HH + k];
        }
        s += __shfl_xor_sync(0xffffffffu, s, 1);
        if (kh == 0) out[fb * 2 + o] = s + fc_b[o];
    }
}

// ---------------------------------------------------------------------------
extern "C" void kernel_launch(void* const* d_in, const int* in_sizes, int n_in,
                              void* d_out, int out_size)
{
    const int*   inputs = (const int*)  d_in[0];
    // d_in[1] = lengths : unused by the reference
    const float* embed  = (const float*)d_in[2];
    const float* w_ih   = (const float*)d_in[3];
    const float* w_hh   = (const float*)d_in[4];
    const float* b_ih   = (const float*)d_in[5];
    const float* b_hh   = (const float*)d_in[6];
    const float* fc_w   = (const float*)d_in[7];
    const float* fc_b   = (const float*)d_in[8];
    float* out = (float*)d_out;

    cudaFuncSetAttribute(lstm_kernel, cudaFuncAttributeMaxDynamicSharedMemorySize, SMEM_F);

    prep_kernel<<<(GG * EE + 255) / 256, 256>>>(w_ih, w_hh);
    lstm_kernel<<<dim3(NTILES, BB), NTHREADS, SMEM_F>>>(inputs, embed, b_ih, b_hh,
                                                        fc_w, fc_b, out);
}

// round 14
// speedup vs baseline: 1.1217x; 1.0166x over previous
#include <cuda_runtime.h>
#include <cuda_bf16.h>
#include <math.h>

#define BB   64
#define SS   512
#define EE   128
#define HH   128
#define GG   512          // 4*H
#define FWW  6
#define WW   507          // S - FW + 1
#define MT   64           // windows per tile (2 halves of 32)
#define NTHREADS 256
#define NTILES 8          // 8*64 >= 507 (tiles per batch row)
#define TOTTILES (NTILES*BB)   // 512 work items
#define PCTAS 148         // persistent CTAs (1 per SM)

#define W_BYTES (GG*EE*2)        // 131072: resident bf16 weight (w_ih, then w_hh)
#define A_ROWS  80               // emb tile rows (69 real, clamped) / h tile (64 rows)
#define A_BYTES (A_ROWS*256)     // 20480
#define X_ROWS  69               // tokens w0..w0+68
#define X_STRIDE 1040            // 512 bf16 + 16B pad
#define X_BYTES (X_ROWS*X_STRIDE)        // 71760
#define SMEM_F  (W_BYTES + A_BYTES + X_BYTES)   // 223312 <= 227KB

// Scratch (device globals: allocation is forbidden)
__device__ __align__(16) __nv_bfloat16 g_wih16[GG * EE];
__device__ __align__(16) __nv_bfloat16 g_whh16[GG * HH];
__device__ unsigned g_featu[BB * HH];   // order-encoded float, atomicMax pooling
__device__ unsigned g_work;             // tile work queue
__device__ unsigned g_done;             // CTA completion counter

// ---------------------------------------------------------------------------
__device__ __forceinline__ unsigned sptr(const void* p) {
    return (unsigned)__cvta_generic_to_shared(p);
}
__device__ __forceinline__ float tanha_(float x) {
    float y; asm("tanh.approx.f32 %0, %1;" : "=f"(y) : "f"(x)); return y;
}
__device__ __forceinline__ float sigm_(float x) {
    return fmaf(0.5f, tanha_(0.5f * x), 0.5f);
}
__device__ __forceinline__ unsigned encf_(float x) {
    unsigned u = __float_as_uint(x);
    return (u & 0x80000000u) ? ~u : (u | 0x80000000u);
}
__device__ __forceinline__ float decf_(unsigned k) {
    return __uint_as_float((k & 0x80000000u) ? (k & 0x7fffffffu) : ~k);
}
__device__ __forceinline__ void ldsm4(unsigned* r, unsigned addr) {
    asm volatile("ldmatrix.sync.aligned.m8n8.x4.shared.b16 {%0,%1,%2,%3}, [%4];"
                 : "=r"(r[0]), "=r"(r[1]), "=r"(r[2]), "=r"(r[3]) : "r"(addr));
}
__device__ __forceinline__ void mma_bf16(float* d, const unsigned* a, unsigned b0, unsigned b1) {
    asm("mma.sync.aligned.m16n8k16.row.col.f32.bf16.bf16.f32 "
        "{%0,%1,%2,%3},{%4,%5,%6,%7},{%8,%9},{%0,%1,%2,%3};"
        : "+f"(d[0]), "+f"(d[1]), "+f"(d[2]), "+f"(d[3])
        : "r"(a[0]), "r"(a[1]), "r"(a[2]), "r"(a[3]), "r"(b0), "r"(b1));
}
__device__ __forceinline__ unsigned packbf2(float lo, float hi) {
    __nv_bfloat162 p = __float22bfloat162_rn(make_float2(lo, hi));
    return *reinterpret_cast<unsigned*>(&p);
}
__device__ __forceinline__ float2 unpackbf2(unsigned u) {
    return __bfloat1622float2(*reinterpret_cast<__nv_bfloat162*>(&u));
}

// ---------------------------------------------------------------------------
// Kernel 0: weights fp32 -> bf16; reset pool accumulators + counters
// ---------------------------------------------------------------------------
__global__ void prep_kernel(const float* __restrict__ w_ih, const float* __restrict__ w_hh) {
    int i = blockIdx.x * blockDim.x + threadIdx.x;
    if (i < GG * EE) {
        g_wih16[i] = __float2bfloat16(w_ih[i]);
        g_whh16[i] = __float2bfloat16(w_hh[i]);
    }
    if (i < BB * HH) g_featu[i] = 0u;
    if (i == 0) { g_work = 0u; g_done = 0u; }
}

// ---------------------------------------------------------------------------
// Stage a full 512x128 bf16 weight matrix into smem, 16B-chunk swizzled
// ---------------------------------------------------------------------------
__device__ __forceinline__ void stage_w(const __nv_bfloat16* __restrict__ src, char* w_sc, int tid) {
    const uint4* s = (const uint4*)src;
    uint4* d = (uint4*)w_sc;
    #pragma unroll
    for (int i = 0; i < 32; ++i) {
        int id  = i * 256 + tid;
        int gs  = id >> 11;
        int rem = id & 2047;
        int n   = rem >> 4;
        int c   = rem & 15;
        d[gs * 2048 + n * 16 + (c ^ (n & 7))] = s[id];
    }
}

// ---------------------------------------------------------------------------
// Load X rows [row0..row0+32) into accumulators (smem -> regs, bf16 -> f32)
// ---------------------------------------------------------------------------
__device__ __forceinline__ void load_x(const char* x_sc, int row0, int g, int tq, int nw0,
                                       float (&acc)[4][2][2][4]) {
    #pragma unroll
    for (int mt = 0; mt < 2; ++mt)
        #pragma unroll
        for (int hh = 0; hh < 2; ++hh) {
            const char* xr = x_sc + (row0 + mt * 16 + g + 8 * hh) * X_STRIDE;
            #pragma unroll
            for (int gs = 0; gs < 4; ++gs)
                #pragma unroll
                for (int nt = 0; nt < 2; ++nt) {
                    unsigned u = *(const unsigned*)(xr + (gs * 128 + nw0 + nt * 8 + 2 * tq) * 2);
                    float2 v = unpackbf2(u);
                    acc[gs][mt][nt][2 * hh]     = v.x;
                    acc[gs][mt][nt][2 * hh + 1] = v.y;
                }
        }
}

// ---------------------------------------------------------------------------
// One phase: GEMM of one half interleaved with the cell update of the OTHER
// half (independent rows -> tensor/MUFU pipes overlap).
// CM: 0 = no cell, 1 = cell + store h to smem, 2 = cell + pool max
// ---------------------------------------------------------------------------
template<bool DO_GEMM, int CM>
__device__ __forceinline__ void run_phase(
    unsigned aB0, unsigned aB1, unsigned bB,
    float (&accG)[4][2][2][4], float (&accC)[4][2][2][4],
    float (&cC)[2][2][4], float (&pmax)[2][2],
    char* a_store, int g, int tq, int rs, int qb, int qh, int nw0,
    int wrow0, int wlim)
{
    #pragma unroll
    for (int ks = 0; ks < 8; ++ks) {
        if (DO_GEMM) {
            unsigned af0[4], af1[4];
            unsigned ca = ((unsigned)((2 * ks + qh) ^ rs)) << 4;
            ldsm4(af0, aB0 + ca);
            ldsm4(af1, aB1 + ca);
            unsigned cb = ((unsigned)((2 * ks + qb) ^ rs)) << 4;
            #pragma unroll
            for (int gs = 0; gs < 4; ++gs) {
                unsigned bf[4];
                ldsm4(bf, bB + gs * 32768 + cb);
                mma_bf16(accG[gs][0][0], af0, bf[0], bf[1]);
                mma_bf16(accG[gs][0][1], af0, bf[2], bf[3]);
                mma_bf16(accG[gs][1][0], af1, bf[0], bf[1]);
                mma_bf16(accG[gs][1][1], af1, bf[2], bf[3]);
            }
        }
        if (CM) {
            const int mt = ks >> 2, nt = (ks >> 1) & 1, hh = ks & 1;
            float h0, h1;
            {
                float gi = accC[0][mt][nt][2 * hh], gf = accC[1][mt][nt][2 * hh];
                float gg = accC[2][mt][nt][2 * hh], go = accC[3][mt][nt][2 * hh];
                float cn = sigm_(gf) * cC[mt][nt][2 * hh] + sigm_(gi) * tanha_(gg);
                cC[mt][nt][2 * hh] = cn;
                h0 = sigm_(go) * tanha_(cn);
            }
            {
                float gi = accC[0][mt][nt][2 * hh + 1], gf = accC[1][mt][nt][2 * hh + 1];
                float gg = accC[2][mt][nt][2 * hh + 1], go = accC[3][mt][nt][2 * hh + 1];
                float cn = sigm_(gf) * cC[mt][nt][2 * hh + 1] + sigm_(gi) * tanha_(gg);
                cC[mt][nt][2 * hh + 1] = cn;
                h1 = sigm_(go) * tanha_(cn);
            }
            if (CM == 1) {
                int r   = mt * 16 + g + 8 * hh;
                int cb0 = (nw0 >> 3) + nt;
                *(unsigned*)(a_store + r * 256 + ((cb0 ^ g) << 4) + 4 * tq) = packbf2(h0, h1);
            } else {
                if (wrow0 + mt * 16 + g + 8 * hh < wlim) {   // exclude invalid windows
                    pmax[nt][0] = fmaxf(pmax[nt][0], h0);
                    pmax[nt][1] = fmaxf(pmax[nt][1], h1);
                }
            }
        }
    }
}

// ---------------------------------------------------------------------------
// Persistent fused kernel: work-queue over 512 tiles; per tile:
// X = emb@w_ih^T + bias (smem), 6-step half-pipelined LSTM, pool; then FC.
// ---------------------------------------------------------------------------
__global__ __launch_bounds__(NTHREADS, 1)
void lstm_kernel(const int* __restrict__ inputs,
                 const float* __restrict__ embed,
                 const float* __restrict__ b_ih,
                 const float* __restrict__ b_hh,
                 const float* __restrict__ fc_w,
                 const float* __restrict__ fc_b,
                 float* __restrict__ out)
{
    extern __shared__ char smem[];
    char* w_sc = smem;                       // weights (w_ih, then w_hh)
    char* a_sc = smem + W_BYTES;             // emb tile (80 rows) / h tiles (rows 0..63)
    char* x_sc = smem + W_BYTES + A_BYTES;   // X: 69 rows x X_STRIDE

    const int tid  = threadIdx.x;
    const int lane = tid & 31;
    const int wid  = tid >> 5;
    const int g    = lane >> 2;
    const int tq   = lane & 3;
    const int rs   = lane & 7;
    const int qb   = (lane >> 3) & 1;
    const int qh   = (lane >> 4) & 1;
    const int nw0  = wid * 16;               // warp's 16-col slice per gate chunk

    // bias (tile-independent, hoisted out of the work loop)
    float bias[4][2][2];
    #pragma unroll
    for (int gs = 0; gs < 4; ++gs)
        #pragma unroll
        for (int nt = 0; nt < 2; ++nt) {
            int col = gs * 128 + nw0 + nt * 8 + 2 * tq;
            float2 bi = *(const float2*)&b_ih[col];
            float2 bh = *(const float2*)&b_hh[col];
            bias[gs][nt][0] = bi.x + bh.x;
            bias[gs][nt][1] = bi.y + bh.y;
        }

    unsigned aS = sptr(a_sc), wS = sptr(w_sc);
    unsigned bB   = wS + (nw0 + rs + 8 * qh) * 256;
    unsigned aA0  = aS + (rs + 8 * qb) * 256;          // half0 h frags
    unsigned aA1  = aA0 + 4096;
    unsigned aB0_ = aS + 8192 + (rs + 8 * qb) * 256;   // half1 h frags
    unsigned aB1_ = aB0_ + 4096;

    __shared__ unsigned s_tile;

    for (;;) {
        if (tid == 0) s_tile = atomicAdd(&g_work, 1u);
        __syncthreads();                 // broadcast tile; prior tile's smem reads done
        const unsigned tile = s_tile;
        if (tile >= TOTTILES) break;

        const int b    = (int)(tile >> 3);        // batch row
        const int w0   = (int)(tile & 7) * MT;    // window base
        const int wlim = WW - w0;                 // valid local windows

        // ---- stage w_ih + gather embeddings ----
        stage_w(g_wih16, w_sc, tid);
        {
            // rows 0..63: 4 threads/row, 32 cols each
            int r = tid >> 2, th = tid & 3;
            int tok = min(w0 + r, SS - 1);
            const float4* erow = (const float4*)(embed + (size_t)inputs[b * SS + tok] * EE) + th * 8;
            #pragma unroll
            for (int j = 0; j < 4; ++j) {
                float4 v0 = erow[2 * j], v1 = erow[2 * j + 1];
                uint4 u;
                u.x = packbf2(v0.x, v0.y); u.y = packbf2(v0.z, v0.w);
                u.z = packbf2(v1.x, v1.y); u.w = packbf2(v1.z, v1.w);
                int c = th * 4 + j;
                *(uint4*)(a_sc + r * 256 + ((c ^ (r & 7)) << 4)) = u;
            }
            // rows 64..79: 16 threads/row, 8 cols each
            int r2 = 64 + (tid >> 4), th2 = tid & 15;
            int tok2 = min(w0 + r2, SS - 1);
            const float4* erow2 = (const float4*)(embed + (size_t)inputs[b * SS + tok2] * EE) + th2 * 2;
            float4 w0v = erow2[0], w1v = erow2[1];
            uint4 u2;
            u2.x = packbf2(w0v.x, w0v.y); u2.y = packbf2(w0v.z, w0v.w);
            u2.z = packbf2(w1v.x, w1v.y); u2.w = packbf2(w1v.z, w1v.w);
            *(uint4*)(a_sc + r2 * 256 + ((th2 ^ (r2 & 7)) << 4)) = u2;
        }
        __syncthreads();   // emb + w_ih staged

        // ---- X = emb @ w_ih^T + bias, three 32-row passes ----
        float accA[4][2][2][4], accB[4][2][2][4];
        float cA[2][2][4] = {}, cB[2][2][4] = {};
        float pmax[2][2] = {{-3.4e38f, -3.4e38f}, {-3.4e38f, -3.4e38f}};

        #pragma unroll
        for (int p = 0; p < 3; ++p) {
            #pragma unroll
            for (int gs = 0; gs < 4; ++gs)
                #pragma unroll
                for (int nt = 0; nt < 2; ++nt)
                    #pragma unroll
                    for (int mt = 0; mt < 2; ++mt) {
                        accA[gs][mt][nt][0] = bias[gs][nt][0]; accA[gs][mt][nt][1] = bias[gs][nt][1];
                        accA[gs][mt][nt][2] = bias[gs][nt][0]; accA[gs][mt][nt][3] = bias[gs][nt][1];
                    }
            unsigned aP0 = aS + (32 * p + rs + 8 * qb) * 256;
            unsigned aP1 = aP0 + 4096;
            run_phase<true, 0>(aP0, aP1, bB, accA, accB, cB, pmax, a_sc,
                               g, tq, rs, qb, qh, nw0, 0, 0);
            #pragma unroll
            for (int gs = 0; gs < 4; ++gs)
                #pragma unroll
                for (int mt = 0; mt < 2; ++mt)
                    #pragma unroll
                    for (int hh = 0; hh < 2; ++hh) {
                        int r = 32 * p + mt * 16 + g + 8 * hh;
                        if (r < X_ROWS) {
                            char* xr = x_sc + r * X_STRIDE;
                            #pragma unroll
                            for (int nt = 0; nt < 2; ++nt)
                                *(unsigned*)(xr + (gs * 128 + nw0 + nt * 8 + 2 * tq) * 2) =
                                    packbf2(accA[gs][mt][nt][2 * hh], accA[gs][mt][nt][2 * hh + 1]);
                        }
                    }
        }

        __syncthreads();              // all w_ih reads + emb reads done
        stage_w(g_whh16, w_sc, tid);  // W := w_hh
        __syncthreads();              // w_hh + X visible

        // ---- t = 0 peel: gates = X only (h = 0) ----
        load_x(x_sc, 0, g, tq, nw0, accA);
        load_x(x_sc, 32, g, tq, nw0, accB);
        run_phase<false, 1>(0, 0, 0, accB, accA, cA, pmax, a_sc,
                            g, tq, rs, qb, qh, nw0, 0, wlim);   // cell_A(0) -> store hA
        load_x(x_sc, 1, g, tq, nw0, accA);                      // hoisted X_A(1)
        __syncthreads();

        // ---- steps 1..5 ----
        for (int t = 1; t < FWW; ++t) {
            // P1: GEMM_A(t) || cell_B(t-1) + store hB ; then hoist X_B(t)
            run_phase<true, 1>(aA0, aA1, bB, accA, accB, cB, pmax, a_sc + 8192,
                               g, tq, rs, qb, qh, nw0, 32, wlim);
            load_x(x_sc, 32 + t, g, tq, nw0, accB);
            __syncthreads();

            if (t < FWW - 1) {
                // P2: GEMM_B(t) || cell_A(t) + store hA ; then hoist X_A(t+1)
                run_phase<true, 1>(aB0_, aB1_, bB, accB, accA, cA, pmax, a_sc,
                                   g, tq, rs, qb, qh, nw0, 0, wlim);
                load_x(x_sc, t + 1, g, tq, nw0, accA);
                __syncthreads();
            } else {
                // final: GEMM_B(5) || cell_A(5)->pool, then cell_B(5)->pool
                run_phase<true, 2>(aB0_, aB1_, bB, accB, accA, cA, pmax, a_sc,
                                   g, tq, rs, qb, qh, nw0, 0, wlim);
                run_phase<false, 2>(0, 0, 0, accA, accB, cB, pmax, a_sc,
                                    g, tq, rs, qb, qh, nw0, 32, wlim);
            }
        }

        // ---- pool: shfl-reduce over rows (g), one atomicMax per column ----
        #pragma unroll
        for (int nt = 0; nt < 2; ++nt)
            #pragma unroll
            for (int e = 0; e < 2; ++e) {
                float m = pmax[nt][e];
                m = fmaxf(m, __shfl_xor_sync(0xffffffffu, m, 4));
                m = fmaxf(m, __shfl_xor_sync(0xffffffffu, m, 8));
                m = fmaxf(m, __shfl_xor_sync(0xffffffffu, m, 16));
                pmax[nt][e] = m;
            }
        if (g == 0) {
            #pragma unroll
            for (int nt = 0; nt < 2; ++nt)
                #pragma unroll
                for (int e = 0; e < 2; ++e)
                    atomicMax(&g_featu[b * HH + nw0 + nt * 8 + 2 * tq + e], encf_(pmax[nt][e]));
        }
        // loop-top __syncthreads() guards smem reuse for the next tile
    }

    // ---- last CTA computes the FC ----
    __threadfence();
    __shared__ unsigned s_last;
    if (tid == 0) {
        unsigned old = atomicAdd(&g_done, 1u);
        s_last = (old == (unsigned)(PCTAS - 1)) ? 1u : 0u;
    }
    __syncthreads();
    if (s_last) {
        int pair = tid >> 1;          // 0..127
        int fb   = pair >> 1;         // batch
        int o    = pair & 1;          // output class
        int kh   = tid & 1;           // k half
        float s = 0.0f;
        #pragma unroll 8
        for (int k = kh * 64; k < kh * 64 + 64; ++k) {
            unsigned enc = atomicAdd(&g_featu[fb * HH + k], 0u);   // coherent read
            s += decf_(enc) * fc_w[o * HH + k];
        }
        s += __shfl_xor_sync(0xffffffffu, s, 1);
        if (kh == 0) out[fb * 2 + o] = s + fc_b[o];
    }
}

// ---------------------------------------------------------------------------
extern "C" void kernel_launch(void* const* d_in, const int* in_sizes, int n_in,
                              void* d_out, int out_size)
{
    const int*   inputs = (const int*)  d_in[0];
    // d_in[1] = lengths : unused by the reference
    const float* embed  = (const float*)d_in[2];
    const float* w_ih   = (const float*)d_in[3];
    const float* w_hh   = (const float*)d_in[4];
    const float* b_ih   = (const float*)d_in[5];
    const float* b_hh   = (const float*)d_in[6];
    const float* fc_w   = (const float*)d_in[7];
    const float* fc_b   = (const float*)d_in[8];
    float* out = (float*)d_out;

    cudaFuncSetAttribute(lstm_kernel, cudaFuncAttributeMaxDynamicSharedMemorySize, SMEM_F);

    prep_kernel<<<(GG * EE + 255) / 256, 256>>>(w_ih, w_hh);
    lstm_kernel<<<PCTAS, NTHREADS, SMEM_F>>>(inputs, embed, b_ih, b_hh,
                                             fc_w, fc_b, out);
}